// round 1
// baseline (speedup 1.0000x reference)
#include <cuda_runtime.h>
#include <cstdint>

// Problem constants
#define BATCH 8
#define SEQ   2048
#define DIM   768
#define MROWS (BATCH*SEQ)          // 16384

// Scratch (module-load allocated; allowed per harness rules)
__device__ float g_q[(size_t)BATCH*SEQ*DIM];
__device__ float g_k[(size_t)BATCH*SEQ*DIM];
__device__ float g_v[(size_t)BATCH*SEQ*DIM];
__device__ float g_s[(size_t)BATCH*SEQ*SEQ];

// ---------------------------------------------------------------------------
// Packed f32x2 helpers (sm_103a FFMA2 — 2x fp32 FMA throughput vs FFMA-3reg)
// ---------------------------------------------------------------------------
__device__ __forceinline__ unsigned long long pack_dup(float a) {
    unsigned long long r;
    asm("mov.b64 %0, {%1, %1};" : "=l"(r) : "f"(a));
    return r;
}
__device__ __forceinline__ void ffma2(unsigned long long& acc,
                                      unsigned long long a,
                                      unsigned long long b) {
    asm("fma.rn.f32x2 %0, %1, %2, %0;" : "+l"(acc) : "l"(a), "l"(b));
}

// ---------------------------------------------------------------------------
// Tiled GEMM: C[M,N] = A[M,K] * op(B)
//   BT=true : B is [N,K] row-major (NT gemm, C = A * B^T)
//   BT=false: B is [K,N] row-major (NN gemm, C = A * B)
// Block tile 128x128, K-tile 16, 256 threads, 8x8 microtile per thread.
// All dims must be multiples of the tile sizes (they are for this problem).
// ---------------------------------------------------------------------------
template<bool BT>
__global__ __launch_bounds__(256)
void gemm128(const float* __restrict__ A, const float* __restrict__ B,
             float* __restrict__ C, int M, int N, int K,
             size_t sA, size_t sB, size_t sC)
{
    A += (size_t)blockIdx.z * sA;
    B += (size_t)blockIdx.z * sB;
    C += (size_t)blockIdx.z * sC;

    __shared__ float As[16][128];
    __shared__ float Bs[16][128];

    const int t  = threadIdx.x;
    const int tx = t & 15;          // 0..15  (column group)
    const int ty = t >> 4;          // 0..15  (row group)
    const int rowBlk = blockIdx.y * 128;
    const int colBlk = blockIdx.x * 128;

    // A-tile (and NT B-tile) loader mapping: 64 rows per pass, 4 floats per row
    const int lr = t >> 2;          // 0..63
    const int lc = (t & 3) * 4;     // 0,4,8,12

    unsigned long long acc[8][4];
    #pragma unroll
    for (int i = 0; i < 8; i++)
        #pragma unroll
        for (int j = 0; j < 4; j++)
            acc[i][j] = 0ull;

    for (int k0 = 0; k0 < K; k0 += 16) {
        // Load A tile [128 x 16], transpose into As[k][m]
        #pragma unroll
        for (int rr = 0; rr < 2; rr++) {
            int r = lr + rr * 64;
            float4 va = *(const float4*)&A[(size_t)(rowBlk + r) * K + k0 + lc];
            As[lc + 0][r] = va.x;
            As[lc + 1][r] = va.y;
            As[lc + 2][r] = va.z;
            As[lc + 3][r] = va.w;
        }
        if (BT) {
            // B [N,K]: tile rows are the output columns; transpose into Bs[k][n]
            #pragma unroll
            for (int rr = 0; rr < 2; rr++) {
                int r = lr + rr * 64;
                float4 vb = *(const float4*)&B[(size_t)(colBlk + r) * K + k0 + lc];
                Bs[lc + 0][r] = vb.x;
                Bs[lc + 1][r] = vb.y;
                Bs[lc + 2][r] = vb.z;
                Bs[lc + 3][r] = vb.w;
            }
        } else {
            // B [K,N]: already k-major; direct copy
            int kr = t >> 4;            // 0..15
            int c  = (t & 15) * 8;      // 0..120
            float4 v0 = *(const float4*)&B[(size_t)(k0 + kr) * N + colBlk + c];
            float4 v1 = *(const float4*)&B[(size_t)(k0 + kr) * N + colBlk + c + 4];
            *(float4*)&Bs[kr][c]     = v0;
            *(float4*)&Bs[kr][c + 4] = v1;
        }
        __syncthreads();

        #pragma unroll
        for (int kk = 0; kk < 16; kk++) {
            float a[8];
            *(float4*)&a[0] = *(const float4*)&As[kk][ty * 8];
            *(float4*)&a[4] = *(const float4*)&As[kk][ty * 8 + 4];

            // 8 B values as 4 packed pairs (contiguous along n in smem)
            ulonglong2 blo = *(const ulonglong2*)&Bs[kk][tx * 8];
            ulonglong2 bhi = *(const ulonglong2*)&Bs[kk][tx * 8 + 4];
            unsigned long long b2[4] = {blo.x, blo.y, bhi.x, bhi.y};

            #pragma unroll
            for (int i = 0; i < 8; i++) {
                unsigned long long a2 = pack_dup(a[i]);
                #pragma unroll
                for (int j = 0; j < 4; j++)
                    ffma2(acc[i][j], a2, b2[j]);
            }
        }
        __syncthreads();
    }

    // Writeback: unpack each 64-bit acc into two fp32
    #pragma unroll
    for (int i = 0; i < 8; i++) {
        float* Crow = &C[(size_t)(rowBlk + ty * 8 + i) * N + colBlk + tx * 8];
        #pragma unroll
        for (int j = 0; j < 4; j++) {
            unsigned long long u = acc[i][j];
            float2 f2;
            f2.x = __uint_as_float((unsigned int)u);
            f2.y = __uint_as_float((unsigned int)(u >> 32));
            *(float2*)&Crow[j * 2] = f2;
        }
    }
}

// ---------------------------------------------------------------------------
// Row softmax (+ post-hoc divide by sqrt(DIM)), one block per score row.
// Row length SEQ=2048 held in smem; 256 threads x 8 elems.
// ---------------------------------------------------------------------------
__global__ __launch_bounds__(256)
void softmax_rows(float* __restrict__ S)
{
    float* row = S + ((size_t)blockIdx.y * SEQ + blockIdx.x) * SEQ;
    __shared__ float buf[SEQ];
    __shared__ float red[256];
    const int t = threadIdx.x;
    float4* b4 = (float4*)buf;

    float m = -3.402823466e38f;
    #pragma unroll
    for (int i = 0; i < 2; i++) {
        float4 v = ((const float4*)row)[t + i * 256];
        b4[t + i * 256] = v;
        m = fmaxf(m, fmaxf(fmaxf(v.x, v.y), fmaxf(v.z, v.w)));
    }
    red[t] = m;
    __syncthreads();
    #pragma unroll
    for (int s = 128; s > 0; s >>= 1) {
        if (t < s) red[t] = fmaxf(red[t], red[t + s]);
        __syncthreads();
    }
    m = red[0];
    __syncthreads();

    float sum = 0.0f;
    #pragma unroll
    for (int i = 0; i < 2; i++) {
        float4 v = b4[t + i * 256];
        v.x = __expf(v.x - m);
        v.y = __expf(v.y - m);
        v.z = __expf(v.z - m);
        v.w = __expf(v.w - m);
        b4[t + i * 256] = v;
        sum += v.x + v.y + v.z + v.w;
    }
    red[t] = sum;
    __syncthreads();
    #pragma unroll
    for (int s = 128; s > 0; s >>= 1) {
        if (t < s) red[t] += red[t + s];
        __syncthreads();
    }
    // softmax / sqrt(DIM): fold into one scale
    const float scale = 1.0f / (red[0] * 27.712812921102035f);  // sqrt(768)

    #pragma unroll
    for (int i = 0; i < 2; i++) {
        float4 v = b4[t + i * 256];
        v.x *= scale; v.y *= scale; v.z *= scale; v.w *= scale;
        ((float4*)row)[t + i * 256] = v;
    }
}

// ---------------------------------------------------------------------------
// Launch
// ---------------------------------------------------------------------------
extern "C" void kernel_launch(void* const* d_in, const int* in_sizes, int n_in,
                              void* d_out, int out_size)
{
    const float* x  = (const float*)d_in[0];
    const float* Wq = (const float*)d_in[1];
    const float* Wk = (const float*)d_in[2];
    const float* Wv = (const float*)d_in[3];
    float* out = (float*)d_out;

    float *q, *k, *v, *s;
    cudaGetSymbolAddress((void**)&q, g_q);
    cudaGetSymbolAddress((void**)&k, g_k);
    cudaGetSymbolAddress((void**)&v, g_v);
    cudaGetSymbolAddress((void**)&s, g_s);

    // 1) QKV projections: [16384,768] = X[16384,768] @ W^T (W is [768,768])
    {
        dim3 grid(DIM / 128, MROWS / 128, 1);
        gemm128<true><<<grid, 256>>>(x, Wq, q, MROWS, DIM, DIM, 0, 0, 0);
        gemm128<true><<<grid, 256>>>(x, Wk, k, MROWS, DIM, DIM, 0, 0, 0);
        gemm128<true><<<grid, 256>>>(x, Wv, v, MROWS, DIM, DIM, 0, 0, 0);
    }

    // 2) Scores: per batch, S[2048,2048] = Q @ K^T
    {
        dim3 grid(SEQ / 128, SEQ / 128, BATCH);
        gemm128<true><<<grid, 256>>>(q, k, s, SEQ, SEQ, DIM,
                                     (size_t)SEQ * DIM, (size_t)SEQ * DIM,
                                     (size_t)SEQ * SEQ);
    }

    // 3) Softmax rows (fused / sqrt(768))
    {
        dim3 grid(SEQ, BATCH, 1);
        softmax_rows<<<grid, 256>>>(s);
    }

    // 4) Output: per batch, O[2048,768] = P @ V
    {
        dim3 grid(DIM / 128, SEQ / 128, BATCH);
        gemm128<false><<<grid, 256>>>(s, v, out, SEQ, DIM, SEQ,
                                      (size_t)SEQ * SEQ, (size_t)SEQ * DIM,
                                      (size_t)SEQ * DIM);
    }
}

// round 3
// speedup vs baseline: 2.6851x; 2.6851x over previous
#include <cuda_runtime.h>
#include <cuda_fp16.h>
#include <cstdint>

#define BATCH 8
#define SEQ   2048
#define DIM   768
#define MROWS (BATCH*SEQ)   // 16384

// ---------------------------------------------------------------------------
// Scratch (static device allocations; allowed)
// ---------------------------------------------------------------------------
__device__ __half g_xh[(size_t)MROWS*DIM];
__device__ __half g_xl[(size_t)MROWS*DIM];
__device__ __half g_wh[(size_t)3*DIM*DIM];
__device__ __half g_wl[(size_t)3*DIM*DIM];
__device__ __half g_qh[(size_t)MROWS*DIM];
__device__ __half g_ql[(size_t)MROWS*DIM];
__device__ __half g_kh[(size_t)MROWS*DIM];
__device__ __half g_kl[(size_t)MROWS*DIM];
__device__ __half g_vth[(size_t)DIM*MROWS];   // V^T: [e][m_global]
__device__ __half g_vtl[(size_t)DIM*MROWS];
__device__ __half g_ph[(size_t)BATCH*SEQ*SEQ];
__device__ __half g_pl[(size_t)BATCH*SEQ*SEQ];
__device__ float  g_s [(size_t)BATCH*SEQ*SEQ];

// ---------------------------------------------------------------------------
// PTX helpers (sm_80+ features only: cp.async, ldmatrix, mma.sync)
// ---------------------------------------------------------------------------
__device__ __forceinline__ uint32_t smem_u32_of(const void* p) {
    uint32_t a;
    asm("{ .reg .u64 t; cvta.to.shared.u64 t, %1; cvt.u32.u64 %0, t; }" : "=r"(a) : "l"(p));
    return a;
}
__device__ __forceinline__ void cp_async16(uint32_t dst, const void* src) {
    asm volatile("cp.async.cg.shared.global [%0], [%1], 16;" :: "r"(dst), "l"(src));
}
#define CP_COMMIT() asm volatile("cp.async.commit_group;" ::: "memory")
#define CP_WAIT1()  asm volatile("cp.async.wait_group 1;" ::: "memory")

__device__ __forceinline__ void ldm_x4(uint32_t* r, uint32_t addr) {
    asm volatile("ldmatrix.sync.aligned.m8n8.x4.shared.b16 {%0,%1,%2,%3}, [%4];"
        : "=r"(r[0]), "=r"(r[1]), "=r"(r[2]), "=r"(r[3]) : "r"(addr));
}
__device__ __forceinline__ void mma16816(float* c, const uint32_t* a, const uint32_t* b) {
    asm volatile("mma.sync.aligned.m16n8k16.row.col.f32.f16.f16.f32 "
        "{%0,%1,%2,%3}, {%4,%5,%6,%7}, {%8,%9}, {%0,%1,%2,%3};"
        : "+f"(c[0]), "+f"(c[1]), "+f"(c[2]), "+f"(c[3])
        : "r"(a[0]), "r"(a[1]), "r"(a[2]), "r"(a[3]), "r"(b[0]), "r"(b[1]));
}
__device__ __forceinline__ uint32_t swz(uint32_t off) { return off ^ ((off >> 3) & 0x70); }
__device__ __forceinline__ unsigned short hbits(__half h) { return __half_as_ushort(h); }

// ---------------------------------------------------------------------------
// HMMA GEMM: C(128x128 tile) = A[M,K] * B[N,K]^T with fp16 hi/lo 3-term split.
// MODE 0: C fp32 [M,N]
// MODE 1: C hi/lo fp16 [M,N]
// MODE 2: C hi/lo fp16 transposed [N][M]  (for V^T)
// Block: 256 threads = 8 warps (2 M x 4 N), warp tile 64x32, k-chunk 64,
// 2-stage cp.async double buffer, SW128-style swizzled smem + ldmatrix.
// ---------------------------------------------------------------------------
#define STAGE_BYTES 65536   // 4 tiles x (128 rows x 128B)
#define SMEM_BYTES  (2*STAGE_BYTES)

template<int MODE>
__global__ __launch_bounds__(256, 1)
void hgemm(const __half* __restrict__ Ah, const __half* __restrict__ Al,
           const __half* __restrict__ Bh, const __half* __restrict__ Bl,
           float* __restrict__ Cf, __half* __restrict__ Ch, __half* __restrict__ Cl,
           int K, int ldA, int ldB, int ldC,
           size_t sA, size_t sB, size_t sC)
{
    extern __shared__ char smem[];
    const uint32_t sbase = smem_u32_of(smem);
    const int t = threadIdx.x;
    const int warp = t >> 5, lane = t & 31;
    const int wm = (warp >> 2) * 64;       // warp M offset (0/64)
    const int wn = (warp & 3) * 32;        // warp N offset (0/32/64/96)
    const int rowBlk = blockIdx.y * 128, colBlk = blockIdx.x * 128;
    const int z = blockIdx.z;

    const __half* Arh = Ah + (size_t)z * sA + (size_t)rowBlk * ldA;
    const __half* Arl = Al + (size_t)z * sA + (size_t)rowBlk * ldA;
    const __half* Brh = Bh + (size_t)z * sB + (size_t)colBlk * ldB;
    const __half* Brl = Bl + (size_t)z * sB + (size_t)colBlk * ldB;

    const int r0 = t >> 3;                 // 0..31 loader row
    const int j0 = t & 7;                  // 0..7  loader col group (16B)

    float acc[4][4][4];
    #pragma unroll
    for (int i = 0; i < 4; i++)
        #pragma unroll
        for (int j = 0; j < 4; j++)
            #pragma unroll
            for (int k = 0; k < 4; k++) acc[i][j][k] = 0.f;

    auto load_chunk = [&](int c, int stg) {
        const int k0 = c << 6;
        const uint32_t sb = sbase + stg * STAGE_BYTES;
        const __half* srcs[4] = { Arh, Arl, Brh, Brl };
        const int lds[4] = { ldA, ldA, ldB, ldB };
        #pragma unroll
        for (int tt = 0; tt < 4; tt++) {
            const __half* g = srcs[tt] + k0 + j0 * 8;
            const int ld = lds[tt];
            const uint32_t tb = sb + tt * 16384;
            #pragma unroll
            for (int i = 0; i < 4; i++) {
                const int r = r0 + i * 32;
                cp_async16(tb + swz((uint32_t)(r * 128 + j0 * 16)), g + (size_t)r * ld);
            }
        }
    };

    const int chunks = K >> 6;
    load_chunk(0, 0);
    CP_COMMIT();

    for (int c = 0; c < chunks; c++) {
        if (c + 1 < chunks) load_chunk(c + 1, (c + 1) & 1);
        CP_COMMIT();
        CP_WAIT1();
        __syncthreads();

        const uint32_t sb = sbase + (c & 1) * STAGE_BYTES;
        #pragma unroll
        for (int kk = 0; kk < 4; kk++) {
            uint32_t ah[4][4], al[4][4], bh[4][2], bl[4][2];
            #pragma unroll
            for (int ma = 0; ma < 4; ma++) {
                const int row = wm + ma * 16 + (lane & 15);
                const uint32_t sw = swz((uint32_t)(row * 128 + kk * 32 + (lane >> 4) * 16));
                ldm_x4(ah[ma], sb + sw);
                ldm_x4(al[ma], sb + 16384 + sw);
            }
            #pragma unroll
            for (int nb = 0; nb < 2; nb++) {
                const int row = wn + nb * 16 + (lane & 15);
                const uint32_t sw = swz((uint32_t)(row * 128 + kk * 32 + (lane >> 4) * 16));
                uint32_t rh[4], rl[4];
                ldm_x4(rh, sb + 32768 + sw);
                ldm_x4(rl, sb + 49152 + sw);
                bh[nb*2+0][0] = rh[0]; bh[nb*2+0][1] = rh[2];
                bh[nb*2+1][0] = rh[1]; bh[nb*2+1][1] = rh[3];
                bl[nb*2+0][0] = rl[0]; bl[nb*2+0][1] = rl[2];
                bl[nb*2+1][0] = rl[1]; bl[nb*2+1][1] = rl[3];
            }
            #pragma unroll
            for (int ma = 0; ma < 4; ma++)
                #pragma unroll
                for (int na = 0; na < 4; na++) {
                    mma16816(acc[ma][na], ah[ma], bh[na]);
                    mma16816(acc[ma][na], ah[ma], bl[na]);
                    mma16816(acc[ma][na], al[ma], bh[na]);
                }
        }
        __syncthreads();
    }

    // ---------------- Epilogue ----------------
    // Frag (ma,na): c0=(r,c) c1=(r,c+1) c2=(r+8,c) c3=(r+8,c+1)
    // with r = wm+ma*16+lane/4, c = wn+na*8+(lane%4)*2
    if (MODE == 0) {
        float* Cb = Cf + (size_t)z * sC;
        #pragma unroll
        for (int ma = 0; ma < 4; ma++) {
            const int r = rowBlk + wm + ma * 16 + (lane >> 2);
            #pragma unroll
            for (int na = 0; na < 4; na++) {
                const int cc = colBlk + wn + na * 8 + (lane & 3) * 2;
                *(float2*)&Cb[(size_t)r * ldC + cc]       = make_float2(acc[ma][na][0], acc[ma][na][1]);
                *(float2*)&Cb[(size_t)(r + 8) * ldC + cc] = make_float2(acc[ma][na][2], acc[ma][na][3]);
            }
        }
    } else {
        __half* Chb = Ch + (size_t)z * sC;
        __half* Clb = Cl + (size_t)z * sC;
        #pragma unroll
        for (int ma = 0; ma < 4; ma++) {
            const int r = rowBlk + wm + ma * 16 + (lane >> 2);
            #pragma unroll
            for (int na = 0; na < 4; na++) {
                const int cc = colBlk + wn + na * 8 + (lane & 3) * 2;
                #pragma unroll
                for (int hrow = 0; hrow < 2; hrow++) {
                    const float v0 = acc[ma][na][hrow * 2 + 0];
                    const float v1 = acc[ma][na][hrow * 2 + 1];
                    const __half h0 = __float2half_rn(v0);
                    const __half h1 = __float2half_rn(v1);
                    const __half l0 = __float2half_rn(v0 - __half2float(h0));
                    const __half l1 = __float2half_rn(v1 - __half2float(h1));
                    const int rr = r + hrow * 8;
                    if (MODE == 1) {
                        *(uint32_t*)&Chb[(size_t)rr * ldC + cc] =
                            (uint32_t)hbits(h0) | ((uint32_t)hbits(h1) << 16);
                        *(uint32_t*)&Clb[(size_t)rr * ldC + cc] =
                            (uint32_t)hbits(l0) | ((uint32_t)hbits(l1) << 16);
                    } else {
                        Chb[(size_t)cc * ldC + rr]       = h0;
                        Chb[(size_t)(cc + 1) * ldC + rr] = h1;
                        Clb[(size_t)cc * ldC + rr]       = l0;
                        Clb[(size_t)(cc + 1) * ldC + rr] = l1;
                    }
                }
            }
        }
    }
}

// ---------------------------------------------------------------------------
// fp32 -> (hi, lo) fp16 split, vectorized
// ---------------------------------------------------------------------------
__global__ __launch_bounds__(256)
void split_hilo(const float* __restrict__ src, __half* __restrict__ hi,
                __half* __restrict__ lo, int n4)
{
    int i = blockIdx.x * blockDim.x + threadIdx.x;
    if (i >= n4) return;
    float4 v = ((const float4*)src)[i];
    float f[4] = { v.x, v.y, v.z, v.w };
    __half h[4], l[4];
    #pragma unroll
    for (int k = 0; k < 4; k++) {
        h[k] = __float2half_rn(f[k]);
        l[k] = __float2half_rn(f[k] - __half2float(h[k]));
    }
    uint2 uh, ul;
    uh.x = (uint32_t)hbits(h[0]) | ((uint32_t)hbits(h[1]) << 16);
    uh.y = (uint32_t)hbits(h[2]) | ((uint32_t)hbits(h[3]) << 16);
    ul.x = (uint32_t)hbits(l[0]) | ((uint32_t)hbits(l[1]) << 16);
    ul.y = (uint32_t)hbits(l[2]) | ((uint32_t)hbits(l[3]) << 16);
    ((uint2*)hi)[i] = uh;
    ((uint2*)lo)[i] = ul;
}

// ---------------------------------------------------------------------------
// Row softmax (+ /sqrt(DIM)) -> P hi/lo fp16
// ---------------------------------------------------------------------------
__global__ __launch_bounds__(256)
void softmax_rows(const float* __restrict__ S, __half* __restrict__ Ph,
                  __half* __restrict__ Pl)
{
    const size_t rbase = ((size_t)blockIdx.y * SEQ + blockIdx.x) * SEQ;
    const float* row = S + rbase;
    __shared__ float buf[SEQ];
    __shared__ float red[256];
    const int t = threadIdx.x;
    float4* b4 = (float4*)buf;

    float m = -3.402823466e38f;
    #pragma unroll
    for (int i = 0; i < 2; i++) {
        float4 v = ((const float4*)row)[t + i * 256];
        b4[t + i * 256] = v;
        m = fmaxf(m, fmaxf(fmaxf(v.x, v.y), fmaxf(v.z, v.w)));
    }
    red[t] = m; __syncthreads();
    #pragma unroll
    for (int s = 128; s > 0; s >>= 1) { if (t < s) red[t] = fmaxf(red[t], red[t + s]); __syncthreads(); }
    m = red[0]; __syncthreads();

    float sum = 0.0f;
    #pragma unroll
    for (int i = 0; i < 2; i++) {
        float4 v = b4[t + i * 256];
        v.x = __expf(v.x - m); v.y = __expf(v.y - m);
        v.z = __expf(v.z - m); v.w = __expf(v.w - m);
        b4[t + i * 256] = v;
        sum += v.x + v.y + v.z + v.w;
    }
    red[t] = sum; __syncthreads();
    #pragma unroll
    for (int s = 128; s > 0; s >>= 1) { if (t < s) red[t] += red[t + s]; __syncthreads(); }
    const float scale = 1.0f / (red[0] * 27.712812921102035f);   // * 1/sqrt(768)

    #pragma unroll
    for (int i = 0; i < 2; i++) {
        float4 v = b4[t + i * 256];
        float f[4] = { v.x * scale, v.y * scale, v.z * scale, v.w * scale };
        __half h[4], l[4];
        #pragma unroll
        for (int k = 0; k < 4; k++) {
            h[k] = __float2half_rn(f[k]);
            l[k] = __float2half_rn(f[k] - __half2float(h[k]));
        }
        uint2 uh, ul;
        uh.x = (uint32_t)hbits(h[0]) | ((uint32_t)hbits(h[1]) << 16);
        uh.y = (uint32_t)hbits(h[2]) | ((uint32_t)hbits(h[3]) << 16);
        ul.x = (uint32_t)hbits(l[0]) | ((uint32_t)hbits(l[1]) << 16);
        ul.y = (uint32_t)hbits(l[2]) | ((uint32_t)hbits(l[3]) << 16);
        ((uint2*)(Ph + rbase))[t + i * 256] = uh;
        ((uint2*)(Pl + rbase))[t + i * 256] = ul;
    }
}

// ---------------------------------------------------------------------------
// Launch
// ---------------------------------------------------------------------------
extern "C" void kernel_launch(void* const* d_in, const int* in_sizes, int n_in,
                              void* d_out, int out_size)
{
    const float* x  = (const float*)d_in[0];
    const float* Wq = (const float*)d_in[1];
    const float* Wk = (const float*)d_in[2];
    const float* Wv = (const float*)d_in[3];
    float* out = (float*)d_out;

    __half *xh, *xl, *wh, *wl, *qh, *ql, *kh, *kl, *vth, *vtl, *ph, *pl;
    float* s;
    cudaGetSymbolAddress((void**)&xh, g_xh);   cudaGetSymbolAddress((void**)&xl, g_xl);
    cudaGetSymbolAddress((void**)&wh, g_wh);   cudaGetSymbolAddress((void**)&wl, g_wl);
    cudaGetSymbolAddress((void**)&qh, g_qh);   cudaGetSymbolAddress((void**)&ql, g_ql);
    cudaGetSymbolAddress((void**)&kh, g_kh);   cudaGetSymbolAddress((void**)&kl, g_kl);
    cudaGetSymbolAddress((void**)&vth, g_vth); cudaGetSymbolAddress((void**)&vtl, g_vtl);
    cudaGetSymbolAddress((void**)&ph, g_ph);   cudaGetSymbolAddress((void**)&pl, g_pl);
    cudaGetSymbolAddress((void**)&s, g_s);

    cudaFuncSetAttribute(hgemm<0>, cudaFuncAttributeMaxDynamicSharedMemorySize, SMEM_BYTES);
    cudaFuncSetAttribute(hgemm<1>, cudaFuncAttributeMaxDynamicSharedMemorySize, SMEM_BYTES);
    cudaFuncSetAttribute(hgemm<2>, cudaFuncAttributeMaxDynamicSharedMemorySize, SMEM_BYTES);

    // 0) fp32 -> hi/lo fp16 splits
    {
        int n4x = MROWS * DIM / 4;
        split_hilo<<<(n4x + 255) / 256, 256>>>(x, xh, xl, n4x);
        int n4w = DIM * DIM / 4;
        split_hilo<<<(n4w + 255) / 256, 256>>>(Wq, wh,                 wl,                 n4w);
        split_hilo<<<(n4w + 255) / 256, 256>>>(Wk, wh + DIM * DIM,     wl + DIM * DIM,     n4w);
        split_hilo<<<(n4w + 255) / 256, 256>>>(Wv, wh + 2 * DIM * DIM, wl + 2 * DIM * DIM, n4w);
    }

    // 1) QKV projections: [16384,768] = X @ W^T
    {
        dim3 grid(DIM / 128, MROWS / 128, 1);
        hgemm<1><<<grid, 256, SMEM_BYTES>>>(xh, xl, wh, wl,
            nullptr, qh, ql, DIM, DIM, DIM, DIM, 0, 0, 0);
        hgemm<1><<<grid, 256, SMEM_BYTES>>>(xh, xl, wh + DIM * DIM, wl + DIM * DIM,
            nullptr, kh, kl, DIM, DIM, DIM, DIM, 0, 0, 0);
        hgemm<2><<<grid, 256, SMEM_BYTES>>>(xh, xl, wh + 2 * DIM * DIM, wl + 2 * DIM * DIM,
            nullptr, vth, vtl, DIM, DIM, DIM, MROWS, 0, 0, 0);
    }

    // 2) Scores: per batch S[2048,2048] = Q @ K^T (fp32 out)
    {
        dim3 grid(SEQ / 128, SEQ / 128, BATCH);
        hgemm<0><<<grid, 256, SMEM_BYTES>>>(qh, ql, kh, kl,
            s, nullptr, nullptr, DIM, DIM, DIM, SEQ,
            (size_t)SEQ * DIM, (size_t)SEQ * DIM, (size_t)SEQ * SEQ);
    }

    // 3) Softmax (+ /sqrt(768)) -> P hi/lo
    {
        dim3 grid(SEQ, BATCH, 1);
        softmax_rows<<<grid, 256>>>(s, ph, pl);
    }

    // 4) Output: per batch O[2048,768] = P @ (V^T)^T (fp32 out)
    {
        dim3 grid(DIM / 128, SEQ / 128, BATCH);
        hgemm<0><<<grid, 256, SMEM_BYTES>>>(ph, pl, vth, vtl,
            out, nullptr, nullptr, SEQ, SEQ, MROWS, DIM,
            (size_t)SEQ * SEQ, (size_t)SEQ, (size_t)SEQ * DIM);
    }
}